// round 5
// baseline (speedup 1.0000x reference)
#include <cuda_runtime.h>

#define NHID 32

// Staging (written by setup kernel) -> copied into __constant__ kc by a
// D2D async memcpy inside kernel_launch (graph-capturable, no allocation).
// Each entry is a 64-bit duplicated-pair (lo == hi == coefficient) so a single
// const load yields a packed f32x2 operand directly.
__device__   unsigned long long g_stage[NHID * 12];
__constant__ unsigned long long kc[NHID * 12];

struct cpx { float x, y; };

__device__ __forceinline__ void apply1q(cpx* s, cpx m00, cpx m01, cpx m10, cpx m11, int wire)
{
    int st = 1 << (2 - wire);
    for (int i = 0; i < 8; i++) {
        if (i & st) continue;
        cpx a = s[i], b = s[i + st];
        cpx n0 = { m00.x*a.x - m00.y*a.y + m01.x*b.x - m01.y*b.y,
                   m00.x*a.y + m00.y*a.x + m01.x*b.y + m01.y*b.x };
        cpx n1 = { m10.x*a.x - m10.y*a.y + m11.x*b.x - m11.y*b.y,
                   m10.x*a.y + m10.y*a.x + m11.x*b.y + m11.y*b.x };
        s[i] = n0; s[i + st] = n1;
    }
}

__device__ __forceinline__ void applyCRX(cpx* s, float c, float sn, int ctrl, int tgt)
{
    int cs = 1 << (2 - ctrl), ts = 1 << (2 - tgt);
    for (int i = 0; i < 8; i++) {
        if (!(i & cs) || (i & ts)) continue;
        cpx a = s[i], b = s[i + ts];
        s[i]      = { c*a.x + sn*b.y, c*a.y - sn*b.x };
        s[i + ts] = { c*b.x + sn*a.y, c*b.y - sn*a.x };
    }
}

__device__ __forceinline__ unsigned long long dup32(float v)
{
    unsigned int u = __float_as_uint(v);
    return ((unsigned long long)u << 32) | u;
}

// 1 block, 32 threads. Lanes 0-3 build the 4 reachable columns of the fixed
// unitary (j-independent), share via smem; then lane j folds its row.
__global__ void setup_kernel(const float* __restrict__ theta,
                             const float* __restrict__ W1,
                             const float* __restrict__ b1,
                             const float* __restrict__ W2)
{
    __shared__ cpx Vs[4][8];
    int tid = threadIdx.x;

    if (tid < 4) {
        cpx s[8];
        for (int i = 0; i < 8; i++) s[i] = {0.f, 0.f};
        s[tid * 2] = {1.f, 0.f};
        float c, sn;
        sincosf(0.5f * theta[0], &sn, &c);
        apply1q(s, {c,0.f},{0.f,-sn},{0.f,-sn},{c,0.f}, 0);     // RX w0
        sincosf(0.5f * theta[1], &sn, &c);
        apply1q(s, {c,0.f},{-sn,0.f},{sn,0.f},{c,0.f}, 1);      // RY w1
        sincosf(0.5f * theta[2], &sn, &c);
        apply1q(s, {c,-sn},{0.f,0.f},{0.f,0.f},{c,sn}, 2);      // RZ w2
        sincosf(0.5f * theta[3], &sn, &c);
        applyCRX(s, c, sn, 0, 1);                                // CRX(0,1)
        sincosf(0.5f * theta[4], &sn, &c);
        apply1q(s, {c,0.f},{-sn,0.f},{sn,0.f},{c,0.f}, 2);      // RY w2
        sincosf(0.5f * theta[5], &sn, &c);
        apply1q(s, {c,0.f},{0.f,-sn},{0.f,-sn},{c,0.f}, 1);     // RX w1
        sincosf(0.5f * theta[6], &sn, &c);
        applyCRX(s, c, sn, 1, 2);                                // CRX(1,2)
        sincosf(0.5f * theta[7], &sn, &c);
        apply1q(s, {c,-sn},{0.f,0.f},{0.f,0.f},{c,sn}, 0);      // RZ w0
        for (int k = 0; k < 8; k++)
            Vs[tid][k] = (tid >= 2) ? cpx{ s[k].y, -s[k].x } : s[k]; // * (-i)
    }
    __syncwarp();

    int j = tid;
    // M[a][b] = sum_k W1[k,j] * Re(V_a[k] conj(V_b[k]))
    float M[4][4];
    for (int a = 0; a < 4; a++)
        for (int b = 0; b < 4; b++) {
            float m = 0.f;
            for (int k = 0; k < 8; k++)
                m += W1[k * NHID + j] * (Vs[a][k].x * Vs[b][k].x + Vs[a][k].y * Vs[b][k].y);
            M[a][b] = m;
        }

    // Half-angle products over basis (1, cos, sin)
    const float R[2][2][3] = { { {0.5f, 0.5f, 0.f}, {0.f, 0.f, 0.5f} },
                               { {0.f, 0.f, 0.5f}, {0.5f, -0.5f, 0.f} } };
    float K[3][3] = { {0.f,0.f,0.f},{0.f,0.f,0.f},{0.f,0.f,0.f} };
    for (int a = 0; a < 4; a++)
        for (int b = 0; b < 4; b++) {
            int ia = a >> 1, ja = a & 1, ib = b >> 1, jb = b & 1;
            float Mab = M[a][b];
            for (int m = 0; m < 3; m++)
                for (int n = 0; n < 3; n++)
                    K[m][n] += Mab * R[ia][ib][m] * R[ja][jb][n];
        }
    K[0][0] += b1[j];

    // layout per j: [K00 K01 K02 K10 K11 K12 K20 K21 K22 W20 W21 pad]
    for (int t = 0; t < 9; t++) g_stage[j * 12 + t] = dup32(K[t / 3][t % 3]);
    g_stage[j * 12 + 9]  = dup32(W2[j * 2 + 0]);
    g_stage[j * 12 + 10] = dup32(W2[j * 2 + 1]);
    g_stage[j * 12 + 11] = 0ull;
}

// ---- packed f32x2 helpers ----
typedef unsigned long long u64;
__device__ __forceinline__ u64 pk2(float lo, float hi) {
    u64 r; asm("mov.b64 %0, {%1,%2};" : "=l"(r) : "f"(lo), "f"(hi)); return r;
}
__device__ __forceinline__ void upk2(u64 v, float& lo, float& hi) {
    asm("mov.b64 {%0,%1}, %2;" : "=f"(lo), "=f"(hi) : "l"(v));
}
__device__ __forceinline__ u64 ffma2(u64 a, u64 b, u64 c) {
    u64 d; asm("fma.rn.f32x2 %0, %1, %2, %3;" : "=l"(d) : "l"(a), "l"(b), "l"(c)); return d;
}
__device__ __forceinline__ u64 relu2(u64 v) {
    float lo, hi;
    upk2(v, lo, hi);
    return pk2(fmaxf(lo, 0.f), fmaxf(hi, 0.f));
}

// SPT=4, constants in __constant__ (uniform path -> LDCU/UR operands; frees
// one GPR bank slot per FFMA2 so rt drops from 3 to 2).
__global__ void __launch_bounds__(256, 4)
qmlp_kernel(const float* __restrict__ x,
            const float* __restrict__ b2,
            float* __restrict__ out, int B)
{
    int t  = blockIdx.x * blockDim.x + threadIdx.x;
    long long s0 = (long long)t * 4;
    if (s0 >= B) return;

    float bias0 = __ldg(&b2[0]);
    float bias1 = __ldg(&b2[1]);

    if (s0 + 4 <= B) {
        // 4 samples: three coalesced LDG.128; x2 is a global phase (unused)
        const float4* xv = reinterpret_cast<const float4*>(x + s0 * 3);
        float4 XA = xv[0], XB = xv[1], XC = xv[2];
        float x0v[4] = { XA.x, XA.w, XB.z, XC.y };
        float x1v[4] = { XA.y, XB.x, XB.w, XC.z };

        float c0[4], sn0[4], c1[4], sn1[4];
        #pragma unroll
        for (int i = 0; i < 4; i++) {
            __sincosf(x0v[i], &sn0[i], &c0[i]);
            __sincosf(x1v[i], &sn1[i], &c1[i]);
        }

        u64 C0a = pk2(c0[0],  c0[1]),  C0b = pk2(c0[2],  c0[3]);
        u64 S0a = pk2(sn0[0], sn0[1]), S0b = pk2(sn0[2], sn0[3]);
        u64 C1a = pk2(c1[0],  c1[1]),  C1b = pk2(c1[2],  c1[3]);
        u64 S1a = pk2(sn1[0], sn1[1]), S1b = pk2(sn1[2], sn1[3]);

        u64 O0a = pk2(bias0, bias0), O1a = pk2(bias1, bias1);
        u64 O0b = O0a, O1b = O1a;

        #pragma unroll
        for (int j = 0; j < NHID; j++) {
            const u64* k = &kc[j * 12];   // immediate const offsets after unroll

            // Horner: g = t0 + c0*t1 + s0*t2,  t_i = K_i0 + c1*K_i1 + s1*K_i2
            u64 t0a = ffma2(C1a, k[1], k[0]);  t0a = ffma2(S1a, k[2], t0a);
            u64 t1a = ffma2(C1a, k[4], k[3]);  t1a = ffma2(S1a, k[5], t1a);
            u64 t2a = ffma2(C1a, k[7], k[6]);  t2a = ffma2(S1a, k[8], t2a);

            u64 t0b = ffma2(C1b, k[1], k[0]);  t0b = ffma2(S1b, k[2], t0b);
            u64 t1b = ffma2(C1b, k[4], k[3]);  t1b = ffma2(S1b, k[5], t1b);
            u64 t2b = ffma2(C1b, k[7], k[6]);  t2b = ffma2(S1b, k[8], t2b);

            u64 ga = ffma2(C0a, t1a, t0a);  ga = ffma2(S0a, t2a, ga);
            u64 gb = ffma2(C0b, t1b, t0b);  gb = ffma2(S0b, t2b, gb);

            u64 ha = relu2(ga), hb = relu2(gb);

            O0a = ffma2(ha, k[9],  O0a);  O1a = ffma2(ha, k[10], O1a);
            O0b = ffma2(hb, k[9],  O0b);  O1b = ffma2(hb, k[10], O1b);
        }

        float r00, r01, r10, r11;
        upk2(O0a, r00, r10);   // ch0 of samples 0,1
        upk2(O1a, r01, r11);   // ch1 of samples 0,1
        float4 w0 = { r00, r01, r10, r11 };
        upk2(O0b, r00, r10);
        upk2(O1b, r01, r11);
        float4 w1 = { r00, r01, r10, r11 };
        float4* ov = reinterpret_cast<float4*>(out + s0 * 2);
        ov[0] = w0;
        ov[1] = w1;
    } else {
        // generic scalar tail (unused when 4 | B)
        for (long long s = s0; s < B; s++) {
            float xx0 = x[s * 3], xx1 = x[s * 3 + 1];
            float cc0, ss0, cc1, ss1;
            __sincosf(xx0, &ss0, &cc0);
            __sincosf(xx1, &ss1, &cc1);
            float o0 = bias0, o1 = bias1;
            for (int j = 0; j < NHID; j++) {
                const u64* k = &kc[j * 12];
                #define KF(i) __uint_as_float((unsigned int)(k[i] & 0xffffffffull))
                float t0 = KF(0) + KF(1)*cc1 + KF(2)*ss1;
                float t1 = KF(3) + KF(4)*cc1 + KF(5)*ss1;
                float t2 = KF(6) + KF(7)*cc1 + KF(8)*ss1;
                float h = fmaxf(t0 + cc0*t1 + ss0*t2, 0.f);
                o0 += h * KF(9);
                o1 += h * KF(10);
                #undef KF
            }
            out[s * 2]     = o0;
            out[s * 2 + 1] = o1;
        }
    }
}

extern "C" void kernel_launch(void* const* d_in, const int* in_sizes, int n_in,
                              void* d_out, int out_size)
{
    const float* x     = (const float*)d_in[0];
    const float* theta = (const float*)d_in[1];
    const float* W1    = (const float*)d_in[2];
    const float* b1    = (const float*)d_in[3];
    const float* W2    = (const float*)d_in[4];
    const float* b2    = (const float*)d_in[5];
    int B = in_sizes[0] / 3;

    setup_kernel<<<1, 32>>>(theta, W1, b1, W2);

    // Stage -> __constant__ : device-to-device async copy (graph-capturable,
    // no allocation). Ordered after setup_kernel on the same stream.
    void* kc_addr = nullptr;
    void* st_addr = nullptr;
    cudaGetSymbolAddress(&kc_addr, kc);
    cudaGetSymbolAddress(&st_addr, g_stage);
    cudaMemcpyAsync(kc_addr, st_addr, sizeof(unsigned long long) * NHID * 12,
                    cudaMemcpyDeviceToDevice, 0);

    int nthreads = (B + 3) / 4;
    int nblocks  = (nthreads + 255) / 256;
    qmlp_kernel<<<nblocks, 256>>>(x, b2, (float*)d_out, B);
}

// round 6
// speedup vs baseline: 1.1848x; 1.1848x over previous
#include <cuda_runtime.h>
#include <cuda_fp16.h>

#define NHID 32

// fp32 folded coefficients (tail path): per j: 9 K coeffs + W2[j][0..1] + pad
__device__ float g_const[NHID * 12];
// Pre-built B fragments for mma.sync.m16n8k16: [kstep][ntile][reg][lane]
// value = half2( KK[ks*16 + 2t + r*8][j], KK[ks*16 + 2t + 1 + r*8][j] ),
// j = ntile*8 + (lane>>2), t = lane&3.
// KK rows: 0-8 = K_hi, 9-17 = K_hi (x F_lo), 18-26 = K_lo (x F_hi), 27-31 = 0.
__device__ unsigned int g_Bfrag[2][4][2][32];

struct cpx { float x, y; };

__device__ __forceinline__ void apply1q(cpx* s, cpx m00, cpx m01, cpx m10, cpx m11, int wire)
{
    int st = 1 << (2 - wire);
    for (int i = 0; i < 8; i++) {
        if (i & st) continue;
        cpx a = s[i], b = s[i + st];
        cpx n0 = { m00.x*a.x - m00.y*a.y + m01.x*b.x - m01.y*b.y,
                   m00.x*a.y + m00.y*a.x + m01.x*b.y + m01.y*b.x };
        cpx n1 = { m10.x*a.x - m10.y*a.y + m11.x*b.x - m11.y*b.y,
                   m10.x*a.y + m10.y*a.x + m11.x*b.y + m11.y*b.x };
        s[i] = n0; s[i + st] = n1;
    }
}

__device__ __forceinline__ void applyCRX(cpx* s, float c, float sn, int ctrl, int tgt)
{
    int cs = 1 << (2 - ctrl), ts = 1 << (2 - tgt);
    for (int i = 0; i < 8; i++) {
        if (!(i & cs) || (i & ts)) continue;
        cpx a = s[i], b = s[i + ts];
        s[i]      = { c*a.x + sn*b.y, c*a.y - sn*b.x };
        s[i + ts] = { c*b.x + sn*a.y, c*b.y - sn*a.x };
    }
}

// 1 block, 32 threads. Lanes 0-3 build the 4 reachable unitary columns,
// then lane j folds its hidden unit and emits fp32 table + B fragments.
__global__ void setup_kernel(const float* __restrict__ theta,
                             const float* __restrict__ W1,
                             const float* __restrict__ b1,
                             const float* __restrict__ W2)
{
    __shared__ cpx Vs[4][8];
    int tid = threadIdx.x;

    if (tid < 4) {
        cpx s[8];
        for (int i = 0; i < 8; i++) s[i] = {0.f, 0.f};
        s[tid * 2] = {1.f, 0.f};
        float c, sn;
        sincosf(0.5f * theta[0], &sn, &c);
        apply1q(s, {c,0.f},{0.f,-sn},{0.f,-sn},{c,0.f}, 0);     // RX w0
        sincosf(0.5f * theta[1], &sn, &c);
        apply1q(s, {c,0.f},{-sn,0.f},{sn,0.f},{c,0.f}, 1);      // RY w1
        sincosf(0.5f * theta[2], &sn, &c);
        apply1q(s, {c,-sn},{0.f,0.f},{0.f,0.f},{c,sn}, 2);      // RZ w2
        sincosf(0.5f * theta[3], &sn, &c);
        applyCRX(s, c, sn, 0, 1);                                // CRX(0,1)
        sincosf(0.5f * theta[4], &sn, &c);
        apply1q(s, {c,0.f},{-sn,0.f},{sn,0.f},{c,0.f}, 2);      // RY w2
        sincosf(0.5f * theta[5], &sn, &c);
        apply1q(s, {c,0.f},{0.f,-sn},{0.f,-sn},{c,0.f}, 1);     // RX w1
        sincosf(0.5f * theta[6], &sn, &c);
        applyCRX(s, c, sn, 1, 2);                                // CRX(1,2)
        sincosf(0.5f * theta[7], &sn, &c);
        apply1q(s, {c,-sn},{0.f,0.f},{0.f,0.f},{c,sn}, 0);      // RZ w0
        for (int k = 0; k < 8; k++)
            Vs[tid][k] = (tid >= 2) ? cpx{ s[k].y, -s[k].x } : s[k]; // * (-i)
    }
    __syncwarp();

    int j = tid;
    float M[4][4];
    for (int a = 0; a < 4; a++)
        for (int b = 0; b < 4; b++) {
            float m = 0.f;
            for (int k = 0; k < 8; k++)
                m += W1[k * NHID + j] * (Vs[a][k].x * Vs[b][k].x + Vs[a][k].y * Vs[b][k].y);
            M[a][b] = m;
        }

    const float R[2][2][3] = { { {0.5f, 0.5f, 0.f}, {0.f, 0.f, 0.5f} },
                               { {0.f, 0.f, 0.5f}, {0.5f, -0.5f, 0.f} } };
    float K[3][3] = { {0.f,0.f,0.f},{0.f,0.f,0.f},{0.f,0.f,0.f} };
    for (int a = 0; a < 4; a++)
        for (int b = 0; b < 4; b++) {
            int ia = a >> 1, ja = a & 1, ib = b >> 1, jb = b & 1;
            float Mab = M[a][b];
            for (int m = 0; m < 3; m++)
                for (int n = 0; n < 3; n++)
                    K[m][n] += Mab * R[ia][ib][m] * R[ja][jb][n];
        }
    K[0][0] += b1[j];   // feature F0 == 1 carries the bias

    float cf[9];
    for (int t = 0; t < 9; t++) cf[t] = K[t / 3][t % 3];

    // fp32 table for the scalar tail
    for (int t = 0; t < 9; t++) g_const[j * 12 + t] = cf[t];
    g_const[j * 12 + 9]  = W2[j * 2 + 0];
    g_const[j * 12 + 10] = W2[j * 2 + 1];
    g_const[j * 12 + 11] = 0.f;

    // split-f16 coefficients
    float chi[9], clo[9];
    for (int i = 0; i < 9; i++) {
        chi[i] = __half2float(__float2half_rn(cf[i]));
        clo[i] = cf[i] - chi[i];
    }
    int nt = j >> 3, g = j & 7;
    for (int ks = 0; ks < 2; ks++)
        for (int r = 0; r < 2; r++)
            for (int t = 0; t < 4; t++) {
                int r0 = ks * 16 + 2 * t + r * 8;
                float v0, v1;
                // KK row value for col j
                #define KKROW(rr) ((rr) < 9 ? chi[(rr)] : (rr) < 18 ? chi[(rr)-9] : (rr) < 27 ? clo[(rr)-18] : 0.f)
                v0 = KKROW(r0);
                v1 = KKROW(r0 + 1);
                #undef KKROW
                __half2 h2 = __floats2half2_rn(v0, v1);
                g_Bfrag[ks][nt][r][g * 4 + t] = *reinterpret_cast<unsigned int*>(&h2);
            }
}

__device__ __forceinline__ void mma16816(float c[4],
                                         unsigned a0, unsigned a1, unsigned a2, unsigned a3,
                                         unsigned b0, unsigned b1)
{
    asm volatile(
        "mma.sync.aligned.m16n8k16.row.col.f32.f16.f16.f32 "
        "{%0,%1,%2,%3}, {%4,%5,%6,%7}, {%8,%9}, {%0,%1,%2,%3};"
        : "+f"(c[0]), "+f"(c[1]), "+f"(c[2]), "+f"(c[3])
        : "r"(a0), "r"(a1), "r"(a2), "r"(a3), "r"(b0), "r"(b1));
}

// One warp = 32 samples = two m16 tiles. A staged via smem (row stride 40
// halves = 80B -> conflict-free frag loads). Hidden layer on tensor pipe,
// output layer scalar fp32 from D fragments + 4-lane shfl reduce.
__global__ void __launch_bounds__(256)
qmlp_mma(const float* __restrict__ x,
         const float* __restrict__ W2,
         const float* __restrict__ b2,
         float* __restrict__ out, int B)
{
    __shared__ __align__(16) __half sA[8][32 * 40];

    int lane = threadIdx.x & 31;
    int warp = threadIdx.x >> 5;
    long long G = (long long)blockIdx.x * 8 + warp;
    long long base = G * 32;
    if (base >= B) return;

    int g = lane >> 2, t = lane & 3;

    if (base + 32 <= B) {
        // ---- uniform operands (L1-cached) ----
        unsigned bf[2][4][2];
        #pragma unroll
        for (int ks = 0; ks < 2; ks++)
            #pragma unroll
            for (int nt = 0; nt < 4; nt++) {
                bf[ks][nt][0] = __ldg(&g_Bfrag[ks][nt][0][lane]);
                bf[ks][nt][1] = __ldg(&g_Bfrag[ks][nt][1][lane]);
            }
        float2 wA[4], wB[4];
        #pragma unroll
        for (int nt = 0; nt < 4; nt++) {
            int j0 = nt * 8 + 2 * t;
            wA[nt] = __ldg(reinterpret_cast<const float2*>(W2 + (size_t)j0 * 2));
            wB[nt] = __ldg(reinterpret_cast<const float2*>(W2 + (size_t)(j0 + 1) * 2));
        }
        float bias0 = __ldg(&b2[0]);
        float bias1 = __ldg(&b2[1]);

        // ---- per-lane feature row (sample = base + lane) ----
        long long S = base + lane;
        float xa = __ldg(&x[S * 3]);
        float xb = __ldg(&x[S * 3 + 1]);      // x[...+2] is a global phase
        float s0n, c0n, s1n, c1n;
        __sincosf(xa, &s0n, &c0n);
        __sincosf(xb, &s1n, &c1n);
        float F[9] = { 1.f, c1n, s1n, c0n, c0n*c1n, c0n*s1n, s0n, s0n*c1n, s0n*s1n };
        float lo[9];
        #pragma unroll
        for (int i = 0; i < 9; i++) {
            float hf = __half2float(__float2half_rn(F[i]));
            lo[i] = F[i] - hf;
        }
        // column layout: 0-8 F_hi, 9-17 F_lo, 18-26 F_hi, 27-31 zero
        float colv[32];
        #pragma unroll
        for (int c = 0; c < 9;  c++) colv[c]      = F[c];
        #pragma unroll
        for (int c = 0; c < 9;  c++) colv[9 + c]  = lo[c];
        #pragma unroll
        for (int c = 0; c < 9;  c++) colv[18 + c] = F[c];
        #pragma unroll
        for (int c = 27; c < 32; c++) colv[c] = 0.f;

        unsigned w[16];
        #pragma unroll
        for (int k = 0; k < 16; k++) {
            __half2 h2 = __floats2half2_rn(colv[2 * k], colv[2 * k + 1]);
            w[k] = *reinterpret_cast<unsigned int*>(&h2);
        }
        uint4* rp = reinterpret_cast<uint4*>(&sA[warp][lane * 40]);
        rp[0] = make_uint4(w[0],  w[1],  w[2],  w[3]);
        rp[1] = make_uint4(w[4],  w[5],  w[6],  w[7]);
        rp[2] = make_uint4(w[8],  w[9],  w[10], w[11]);
        rp[3] = make_uint4(w[12], w[13], w[14], w[15]);
        __syncwarp();

        const unsigned* sw = reinterpret_cast<const unsigned*>(sA[warp]);  // 20 words/row

        #pragma unroll
        for (int tile = 0; tile < 2; tile++) {
            float acc[4][4];
            #pragma unroll
            for (int nt = 0; nt < 4; nt++)
                #pragma unroll
                for (int c = 0; c < 4; c++) acc[nt][c] = 0.f;

            int r0w = (tile * 16 + g) * 20;
            int r1w = (tile * 16 + g + 8) * 20;
            #pragma unroll
            for (int ks = 0; ks < 2; ks++) {
                unsigned a0 = sw[r0w + ks * 8 + t];
                unsigned a1 = sw[r1w + ks * 8 + t];
                unsigned a2 = sw[r0w + ks * 8 + t + 4];
                unsigned a3 = sw[r1w + ks * 8 + t + 4];
                #pragma unroll
                for (int nt = 0; nt < 4; nt++)
                    mma16816(acc[nt], a0, a1, a2, a3, bf[ks][nt][0], bf[ks][nt][1]);
            }

            // epilogue: relu + W2, per-lane partials over its 8 hidden cols
            float p0 = 0.f, p1 = 0.f, q0 = 0.f, q1 = 0.f;
            #pragma unroll
            for (int nt = 0; nt < 4; nt++) {
                float h0 = fmaxf(acc[nt][0], 0.f);
                float h1 = fmaxf(acc[nt][1], 0.f);
                float h2v = fmaxf(acc[nt][2], 0.f);
                float h3 = fmaxf(acc[nt][3], 0.f);
                p0 += h0 * wA[nt].x + h1 * wB[nt].x;
                p1 += h0 * wA[nt].y + h1 * wB[nt].y;
                q0 += h2v * wA[nt].x + h3 * wB[nt].x;
                q1 += h2v * wA[nt].y + h3 * wB[nt].y;
            }
            // reduce across the 4 lanes sharing row g
            p0 += __shfl_xor_sync(0xffffffffu, p0, 1);
            p0 += __shfl_xor_sync(0xffffffffu, p0, 2);
            p1 += __shfl_xor_sync(0xffffffffu, p1, 1);
            p1 += __shfl_xor_sync(0xffffffffu, p1, 2);
            q0 += __shfl_xor_sync(0xffffffffu, q0, 1);
            q0 += __shfl_xor_sync(0xffffffffu, q0, 2);
            q1 += __shfl_xor_sync(0xffffffffu, q1, 1);
            q1 += __shfl_xor_sync(0xffffffffu, q1, 2);

            if (t == 0) {
                long long r = base + tile * 16 + g;
                float2* ov = reinterpret_cast<float2*>(out);
                ov[r]     = make_float2(p0 + bias0, p1 + bias1);
                ov[r + 8] = make_float2(q0 + bias0, q1 + bias1);
            }
        }
    } else {
        // scalar fp32 tail (unused when 32 | B)
        float bias0 = __ldg(&b2[0]);
        float bias1 = __ldg(&b2[1]);
        for (long long s = base + lane; s < B; s += 32) {
            float xx0 = x[s * 3], xx1 = x[s * 3 + 1];
            float cc0, ss0, cc1, ss1;
            __sincosf(xx0, &ss0, &cc0);
            __sincosf(xx1, &ss1, &cc1);
            float o0 = bias0, o1 = bias1;
            for (int j = 0; j < NHID; j++) {
                const float* K = &g_const[j * 12];
                float t0 = K[0] + K[1]*cc1 + K[2]*ss1;
                float t1 = K[3] + K[4]*cc1 + K[5]*ss1;
                float t2 = K[6] + K[7]*cc1 + K[8]*ss1;
                float h = fmaxf(t0 + cc0*t1 + ss0*t2, 0.f);
                o0 += h * K[9];
                o1 += h * K[10];
            }
            out[s * 2]     = o0;
            out[s * 2 + 1] = o1;
        }
    }
}

extern "C" void kernel_launch(void* const* d_in, const int* in_sizes, int n_in,
                              void* d_out, int out_size)
{
    const float* x     = (const float*)d_in[0];
    const float* theta = (const float*)d_in[1];
    const float* W1    = (const float*)d_in[2];
    const float* b1    = (const float*)d_in[3];
    const float* W2    = (const float*)d_in[4];
    const float* b2    = (const float*)d_in[5];
    int B = in_sizes[0] / 3;

    setup_kernel<<<1, 32>>>(theta, W1, b1, W2);

    int tiles32 = (B + 31) / 32;
    int nblocks = (tiles32 + 7) / 8;
    qmlp_mma<<<nblocks, 256>>>(x, W2, b2, (float*)d_out, B);
}